// round 4
// baseline (speedup 1.0000x reference)
#include <cuda_runtime.h>
#include <cstdint>
#include <cstddef>

// ---------------------------------------------------------------- constants
#define BSZ   4
#define NSEQ  2048
#define KDIM  1024
#define NH    16
#define HS    64
#define MROWS (BSZ*NSEQ)      // 8192

// ---------------------------------------------------------------- scratch
// Q,K,V in [b][h][n][s] head-major layout, A = attention output in [b*n][k]
__device__ __align__(16) float g_Q[BSZ*NH*NSEQ*HS];
__device__ __align__(16) float g_K[BSZ*NH*NSEQ*HS];
__device__ __align__(16) float g_V[BSZ*NH*NSEQ*HS];
__device__ __align__(16) float g_A[MROWS*KDIM];

// ---------------------------------------------------------------- f32x2 helpers
typedef unsigned long long ull;

__device__ __forceinline__ ull pk2(float lo, float hi) {
    ull r; asm("mov.b64 %0, {%1, %2};" : "=l"(r) : "f"(lo), "f"(hi)); return r;
}
__device__ __forceinline__ void unpk2(ull p, float& lo, float& hi) {
    asm("mov.b64 {%0, %1}, %2;" : "=f"(lo), "=f"(hi) : "l"(p));
}
__device__ __forceinline__ ull ffma2(ull a, ull b, ull c) {
    ull d; asm("fma.rn.f32x2 %0, %1, %2, %3;" : "=l"(d) : "l"(a), "l"(b), "l"(c)); return d;
}
__device__ __forceinline__ ull fmul2(ull a, ull b) {
    ull d; asm("mul.rn.f32x2 %0, %1, %2;" : "=l"(d) : "l"(a), "l"(b)); return d;
}

union F4U { float4 f; ull u[2]; };

// ---------------------------------------------------------------- GEMM
// C[m][n] = sum_k A[m][k] * W[n][k]   (i.e. y = A @ W^T), M=8192, N=K=1024
// mode 0/1/2: scatter C into g_Q/g_K/g_V as [b][h][n][s]
// mode 3:     A := g_A, C -> outp flat [m][n] with +bias
#define BM 128
#define BN 128
#define BKT 16
#define KTILES (KDIM/BKT)   // 64

__global__ __launch_bounds__(256)
void proj_gemm(const float* __restrict__ Ain, const float* __restrict__ W,
               const float* __restrict__ bias, float* __restrict__ outp, int mode)
{
    __shared__ __align__(16) float As[2][BKT][BM];
    __shared__ __align__(16) float Bs[2][BKT][BN];

    const float* A = (mode == 3) ? (const float*)g_A : Ain;

    const int tid = threadIdx.x;
    const int m0 = blockIdx.y * BM;
    const int n0 = blockIdx.x * BN;

    // global-load mapping: each thread loads 8 contiguous floats of one row
    const int lr = tid >> 1;
    const int lc = (tid & 1) * 8;

    const float* Ap = A + (size_t)(m0 + lr) * KDIM + lc;
    const float* Wp = W + (size_t)(n0 + lr) * KDIM + lc;

    // microkernel mapping: 16x16 thread grid, 8x8 output per thread
    const int tx = tid & 15;
    const int ty = tid >> 4;
    const int row0 = ty * 8;
    const int col0 = tx * 8;

    ull acc[4][8];
    #pragma unroll
    for (int r = 0; r < 4; ++r)
        #pragma unroll
        for (int c = 0; c < 8; ++c) acc[r][c] = 0ull;

    // preload tile 0 directly to smem (transposed: As[k][m], Bs[k][n])
    {
        float4 a0 = *(const float4*)(Ap);
        float4 a1 = *(const float4*)(Ap + 4);
        float4 b0 = *(const float4*)(Wp);
        float4 b1 = *(const float4*)(Wp + 4);
        As[0][lc+0][lr]=a0.x; As[0][lc+1][lr]=a0.y; As[0][lc+2][lr]=a0.z; As[0][lc+3][lr]=a0.w;
        As[0][lc+4][lr]=a1.x; As[0][lc+5][lr]=a1.y; As[0][lc+6][lr]=a1.z; As[0][lc+7][lr]=a1.w;
        Bs[0][lc+0][lr]=b0.x; Bs[0][lc+1][lr]=b0.y; Bs[0][lc+2][lr]=b0.z; Bs[0][lc+3][lr]=b0.w;
        Bs[0][lc+4][lr]=b1.x; Bs[0][lc+5][lr]=b1.y; Bs[0][lc+6][lr]=b1.z; Bs[0][lc+7][lr]=b1.w;
    }
    __syncthreads();

    int buf = 0;
    for (int t = 0; t < KTILES; ++t) {
        float4 a0, a1, b0, b1;
        if (t + 1 < KTILES) {
            const float* ap = Ap + (t + 1) * BKT;
            const float* wp = Wp + (t + 1) * BKT;
            a0 = *(const float4*)(ap); a1 = *(const float4*)(ap + 4);
            b0 = *(const float4*)(wp); b1 = *(const float4*)(wp + 4);
        }
        #pragma unroll
        for (int k = 0; k < BKT; ++k) {
            F4U av0, av1, bv0, bv1;
            av0.f = *(const float4*)&As[buf][k][row0];
            av1.f = *(const float4*)&As[buf][k][row0 + 4];
            bv0.f = *(const float4*)&Bs[buf][k][col0];
            bv1.f = *(const float4*)&Bs[buf][k][col0 + 4];
            ull ap_[4] = { av0.u[0], av0.u[1], av1.u[0], av1.u[1] };
            ull bd[8];
            bd[0]=pk2(bv0.f.x,bv0.f.x); bd[1]=pk2(bv0.f.y,bv0.f.y);
            bd[2]=pk2(bv0.f.z,bv0.f.z); bd[3]=pk2(bv0.f.w,bv0.f.w);
            bd[4]=pk2(bv1.f.x,bv1.f.x); bd[5]=pk2(bv1.f.y,bv1.f.y);
            bd[6]=pk2(bv1.f.z,bv1.f.z); bd[7]=pk2(bv1.f.w,bv1.f.w);
            #pragma unroll
            for (int r = 0; r < 4; ++r)
                #pragma unroll
                for (int c = 0; c < 8; ++c)
                    acc[r][c] = ffma2(ap_[r], bd[c], acc[r][c]);
        }
        if (t + 1 < KTILES) {
            __syncthreads();
            const int nb = buf ^ 1;
            As[nb][lc+0][lr]=a0.x; As[nb][lc+1][lr]=a0.y; As[nb][lc+2][lr]=a0.z; As[nb][lc+3][lr]=a0.w;
            As[nb][lc+4][lr]=a1.x; As[nb][lc+5][lr]=a1.y; As[nb][lc+6][lr]=a1.z; As[nb][lc+7][lr]=a1.w;
            Bs[nb][lc+0][lr]=b0.x; Bs[nb][lc+1][lr]=b0.y; Bs[nb][lc+2][lr]=b0.z; Bs[nb][lc+3][lr]=b0.w;
            Bs[nb][lc+4][lr]=b1.x; Bs[nb][lc+5][lr]=b1.y; Bs[nb][lc+6][lr]=b1.z; Bs[nb][lc+7][lr]=b1.w;
            __syncthreads();
            buf = nb;
        }
    }

    float cf[8][8];
    #pragma unroll
    for (int r = 0; r < 4; ++r)
        #pragma unroll
        for (int c = 0; c < 8; ++c)
            unpk2(acc[r][c], cf[2*r][c], cf[2*r+1][c]);

    if (mode == 3) {
        float bb0[8];
        #pragma unroll
        for (int c = 0; c < 8; ++c) bb0[c] = bias[n0 + col0 + c];
        #pragma unroll
        for (int rr = 0; rr < 8; ++rr) {
            size_t dst = (size_t)(m0 + row0 + rr) * KDIM + n0 + col0;
            float4 v0 = make_float4(cf[rr][0]+bb0[0], cf[rr][1]+bb0[1],
                                    cf[rr][2]+bb0[2], cf[rr][3]+bb0[3]);
            float4 v1 = make_float4(cf[rr][4]+bb0[4], cf[rr][5]+bb0[5],
                                    cf[rr][6]+bb0[6], cf[rr][7]+bb0[7]);
            *(float4*)&outp[dst]     = v0;
            *(float4*)&outp[dst + 4] = v1;
        }
    } else {
        float* C = (mode == 0) ? g_Q : ((mode == 1) ? g_K : g_V);
        const int j  = n0 + col0;     // 8-aligned -> stays inside one 64-wide head
        const int hh = j >> 6;
        const int sj = j & 63;
        #pragma unroll
        for (int rr = 0; rr < 8; ++rr) {
            const int m  = m0 + row0 + rr;
            const int bb = m >> 11;        // / 2048
            const int nn = m & 2047;
            size_t dst = ((size_t)(bb * NH + hh) * NSEQ + nn) * HS + sj;
            *(float4*)&C[dst]     = make_float4(cf[rr][0], cf[rr][1], cf[rr][2], cf[rr][3]);
            *(float4*)&C[dst + 4] = make_float4(cf[rr][4], cf[rr][5], cf[rr][6], cf[rr][7]);
        }
    }
}

// ---------------------------------------------------------------- attention
// One block = 64 query rows of one (b,h). Flash-style online softmax over
// 64-key tiles. P tile aliases the K tile -> exactly 48KB static smem.
__global__ __launch_bounds__(256)
void attn_kernel()
{
    __shared__ __align__(16) float Qs[64][64];    // [d][i], pre-scaled by 1/8
    __shared__ __align__(16) float KPs[64][64];   // K phase: [d][j]; P phase: [j][i]
    __shared__ __align__(16) float Vs[64][64];    // [j][c]

    const int tid = threadIdx.x;
    const int bh  = blockIdx.y;                   // b*16 + h
    const int i0  = blockIdx.x * 64;
    const size_t base = (size_t)bh * NSEQ * HS;

    for (int idx = tid; idx < 64*64; idx += 256) {
        int r = idx >> 6, d = idx & 63;
        Qs[d][r] = g_Q[base + (size_t)(i0 + r) * HS + d] * 0.125f;  // 1/sqrt(64)
    }

    const int tx = tid & 15, ty = tid >> 4;
    const int ir = ty * 4;    // local query rows ir..ir+3
    const int jc = tx * 4;    // local cols (keys in S phase, head-dims in O phase)

    ull o[2][4];
    #pragma unroll
    for (int rp = 0; rp < 2; ++rp)
        #pragma unroll
        for (int c = 0; c < 4; ++c) o[rp][c] = 0ull;

    float mrow[4] = { -1e30f, -1e30f, -1e30f, -1e30f };
    float lrow[4] = { 0.f, 0.f, 0.f, 0.f };

    for (int jt = 0; jt < NSEQ/64; ++jt) {
        __syncthreads();   // previous PV done before overwriting KPs/Vs
        const int j0 = jt * 64;
        for (int idx = tid; idx < 64*64; idx += 256) {
            int r = idx >> 6, d = idx & 63;
            KPs[d][r] = g_K[base + (size_t)(j0 + r) * HS + d];
            Vs[r][d]  = g_V[base + (size_t)(j0 + r) * HS + d];
        }
        __syncthreads();

        // ---- S = (Q/8) @ K^T, 4x4 per thread via f32x2
        ull sp[2][4];
        #pragma unroll
        for (int rp = 0; rp < 2; ++rp)
            #pragma unroll
            for (int c = 0; c < 4; ++c) sp[rp][c] = 0ull;

        #pragma unroll 8
        for (int d = 0; d < 64; ++d) {
            F4U a, bq;
            a.f  = *(const float4*)&Qs[d][ir];
            bq.f = *(const float4*)&KPs[d][jc];
            ull bd[4] = { pk2(bq.f.x,bq.f.x), pk2(bq.f.y,bq.f.y),
                          pk2(bq.f.z,bq.f.z), pk2(bq.f.w,bq.f.w) };
            #pragma unroll
            for (int rp = 0; rp < 2; ++rp)
                #pragma unroll
                for (int c = 0; c < 4; ++c)
                    sp[rp][c] = ffma2(a.u[rp], bd[c], sp[rp][c]);
        }

        float sv[4][4];
        #pragma unroll
        for (int rp = 0; rp < 2; ++rp)
            #pragma unroll
            for (int c = 0; c < 4; ++c)
                unpk2(sp[rp][c], sv[2*rp][c], sv[2*rp+1][c]);

        // ---- online softmax (row reductions across the 16 tx-threads)
        float sc[4];
        #pragma unroll
        for (int r = 0; r < 4; ++r) {
            float v = fmaxf(fmaxf(sv[r][0], sv[r][1]), fmaxf(sv[r][2], sv[r][3]));
            #pragma unroll
            for (int off = 8; off >= 1; off >>= 1)
                v = fmaxf(v, __shfl_xor_sync(0xffffffffu, v, off, 16));
            const float nm = fmaxf(mrow[r], v);
            sc[r] = __expf(mrow[r] - nm);
            float rs = 0.f;
            #pragma unroll
            for (int c = 0; c < 4; ++c) { sv[r][c] = __expf(sv[r][c] - nm); rs += sv[r][c]; }
            #pragma unroll
            for (int off = 8; off >= 1; off >>= 1)
                rs += __shfl_xor_sync(0xffffffffu, rs, off, 16);
            lrow[r] = lrow[r] * sc[r] + rs;
            mrow[r] = nm;
        }
        { // rescale O accumulators
            ull scp[2] = { pk2(sc[0], sc[1]), pk2(sc[2], sc[3]) };
            #pragma unroll
            for (int rp = 0; rp < 2; ++rp)
                #pragma unroll
                for (int c = 0; c < 4; ++c)
                    o[rp][c] = fmul2(o[rp][c], scp[rp]);
        }

        __syncthreads();   // all threads finished reading KPs as K
        #pragma unroll
        for (int c = 0; c < 4; ++c)
            #pragma unroll
            for (int r = 0; r < 4; ++r)
                KPs[jc + c][ir + r] = sv[r][c];   // P stored [j][i]
        __syncthreads();

        // ---- O += P @ V
        #pragma unroll 8
        for (int j = 0; j < 64; ++j) {
            F4U a, bv;
            a.f  = *(const float4*)&KPs[j][ir];
            bv.f = *(const float4*)&Vs[j][jc];
            ull bd[4] = { pk2(bv.f.x,bv.f.x), pk2(bv.f.y,bv.f.y),
                          pk2(bv.f.z,bv.f.z), pk2(bv.f.w,bv.f.w) };
            #pragma unroll
            for (int rp = 0; rp < 2; ++rp)
                #pragma unroll
                for (int c = 0; c < 4; ++c)
                    o[rp][c] = ffma2(a.u[rp], bd[c], o[rp][c]);
        }
    }

    // ---- finalize: O /= l, write to g_A[(b*N + i)][h*64 + c]
    float inv[4];
    #pragma unroll
    for (int r = 0; r < 4; ++r) inv[r] = 1.f / lrow[r];
    {
        ull ip[2] = { pk2(inv[0], inv[1]), pk2(inv[2], inv[3]) };
        #pragma unroll
        for (int rp = 0; rp < 2; ++rp)
            #pragma unroll
            for (int c = 0; c < 4; ++c)
                o[rp][c] = fmul2(o[rp][c], ip[rp]);
    }
    float ov[4][4];
    #pragma unroll
    for (int rp = 0; rp < 2; ++rp)
        #pragma unroll
        for (int c = 0; c < 4; ++c)
            unpk2(o[rp][c], ov[2*rp][c], ov[2*rp+1][c]);

    const int bb = bh >> 4, hh = bh & 15;
    #pragma unroll
    for (int r = 0; r < 4; ++r) {
        size_t dst = ((size_t)bb * NSEQ + i0 + ir + r) * KDIM + hh * HS + jc;
        *(float4*)&g_A[dst] = make_float4(ov[r][0], ov[r][1], ov[r][2], ov[r][3]);
    }
}

// ---------------------------------------------------------------- launch
extern "C" void kernel_launch(void* const* d_in, const int* in_sizes, int n_in,
                              void* d_out, int out_size)
{
    (void)in_sizes; (void)n_in; (void)out_size;
    // metadata order: x, Wk, Wq, Wv, Wu, bu
    const float* x  = (const float*)d_in[0];
    const float* Wk = (const float*)d_in[1];
    const float* Wq = (const float*)d_in[2];
    const float* Wv = (const float*)d_in[3];
    const float* Wu = (const float*)d_in[4];
    const float* bu = (const float*)d_in[5];
    float* out = (float*)d_out;

    dim3 ggrid(KDIM / BN, MROWS / BM);   // (8, 64)
    proj_gemm<<<ggrid, 256>>>(x, Wq, nullptr, nullptr, 0);   // -> g_Q
    proj_gemm<<<ggrid, 256>>>(x, Wk, nullptr, nullptr, 1);   // -> g_K
    proj_gemm<<<ggrid, 256>>>(x, Wv, nullptr, nullptr, 2);   // -> g_V
    attn_kernel<<<dim3(NSEQ/64, BSZ*NH), 256>>>();           // -> g_A
    proj_gemm<<<ggrid, 256>>>(nullptr, Wu, bu, out, 3);      // g_A @ Wu^T + bu
}

// round 8
// speedup vs baseline: 3.4515x; 3.4515x over previous
#include <cuda_runtime.h>
#include <cuda_bf16.h>
#include <cstdint>
#include <cstddef>

// ---------------------------------------------------------------- constants
#define BSZ   4
#define NSEQ  2048
#define KDIM  1024
#define NH    16
#define HS    64
#define MROWS (BSZ*NSEQ)              // 8192
#define QKVN  (BSZ*NH*NSEQ*HS)        // 8388608

// ---------------------------------------------------------------- scratch
__device__ __align__(16) __nv_bfloat16 g_xhi[MROWS*KDIM];
__device__ __align__(16) __nv_bfloat16 g_xlo[MROWS*KDIM];
__device__ __align__(16) __nv_bfloat16 g_whi[KDIM*KDIM];
__device__ __align__(16) __nv_bfloat16 g_wlo[KDIM*KDIM];
__device__ __align__(16) __nv_bfloat16 g_Qh[QKVN], g_Ql[QKVN];
__device__ __align__(16) __nv_bfloat16 g_Kh[QKVN], g_Kl[QKVN];
__device__ __align__(16) __nv_bfloat16 g_Vh[QKVN], g_Vl[QKVN];

// ---------------------------------------------------------------- helpers
__device__ __forceinline__ uint32_t s2u(const void* p) {
    uint32_t a;
    asm("{ .reg .u64 t; cvta.to.shared.u64 t, %1; cvt.u32.u64 %0, t; }" : "=r"(a) : "l"(p));
    return a;
}
__device__ __forceinline__ void cp16(uint32_t dst, const void* src) {
    asm volatile("cp.async.cg.shared.global [%0], [%1], 16;" :: "r"(dst), "l"(src) : "memory");
}
__device__ __forceinline__ void cp_commit() {
    asm volatile("cp.async.commit_group;" ::: "memory");
}
template<int N> __device__ __forceinline__ void cp_wait() {
    asm volatile("cp.async.wait_group %0;" :: "n"(N) : "memory");
}
__device__ __forceinline__ void ldm4(uint32_t* r, uint32_t a) {
    asm volatile("ldmatrix.sync.aligned.m8n8.x4.shared.b16 {%0,%1,%2,%3}, [%4];"
        : "=r"(r[0]), "=r"(r[1]), "=r"(r[2]), "=r"(r[3]) : "r"(a));
}
__device__ __forceinline__ void ldm4t(uint32_t* r, uint32_t a) {
    asm volatile("ldmatrix.sync.aligned.m8n8.x4.trans.shared.b16 {%0,%1,%2,%3}, [%4];"
        : "=r"(r[0]), "=r"(r[1]), "=r"(r[2]), "=r"(r[3]) : "r"(a));
}
__device__ __forceinline__ void mma16816(float* c, const uint32_t* a, uint32_t b0, uint32_t b1) {
    asm volatile("mma.sync.aligned.m16n8k16.row.col.f32.bf16.bf16.f32 "
        "{%0,%1,%2,%3}, {%4,%5,%6,%7}, {%8,%9}, {%0,%1,%2,%3};"
        : "+f"(c[0]), "+f"(c[1]), "+f"(c[2]), "+f"(c[3])
        : "r"(a[0]), "r"(a[1]), "r"(a[2]), "r"(a[3]), "r"(b0), "r"(b1));
}
// pack (f0 -> low bf16, f1 -> high bf16)
__device__ __forceinline__ uint32_t pack2(float f0, float f1) {
    uint32_t r; asm("cvt.rn.bf16x2.f32 %0, %1, %2;" : "=r"(r) : "f"(f1), "f"(f0)); return r;
}
__device__ __forceinline__ float lo2f(uint32_t p) { return __uint_as_float(p << 16); }
__device__ __forceinline__ float hi2f(uint32_t p) { return __uint_as_float(p & 0xffff0000u); }
__device__ __forceinline__ void split2(float f0, float f1, uint32_t& h, uint32_t& l) {
    h = pack2(f0, f1);
    l = pack2(f0 - lo2f(h), f1 - hi2f(h));
}

// ---------------------------------------------------------------- converts
// sel 0: x -> g_xhi/g_xlo   sel 1: W -> g_whi/g_wlo
__global__ __launch_bounds__(256) void cvt(const float* __restrict__ src, int sel)
{
    size_t i = ((size_t)blockIdx.x * 256 + threadIdx.x) * 4;
    float4 v = *(const float4*)(src + i);
    uint32_t h0, l0, h1, l1;
    split2(v.x, v.y, h0, l0);
    split2(v.z, v.w, h1, l1);
    __nv_bfloat16* dh = sel ? g_whi : g_xhi;
    __nv_bfloat16* dl = sel ? g_wlo : g_xlo;
    uint2 H = make_uint2(h0, h1), L = make_uint2(l0, l1);
    *(uint2*)(dh + i) = H;
    *(uint2*)(dl + i) = L;
}

// ---------------------------------------------------------------- HMMA GEMM
// C[m][n] = sum_k A[m][k]*W[n][k], hi/lo compensated (3 MMA products).
// mode 0/1/2 -> split-write g_{Q,K,V}{h,l} in [b][h][n][s] (Q scaled 0.125)
// mode 3     -> outp[m][n] = C + bias[n]  (fp32)
#define G_TB   10240                  // 128 rows * 80B (64B data + 16B pad)
#define G_STG  (4*G_TB)               // Ahi, Alo, Bhi, Blo
#define G_SMEM (2*G_STG)              // 81920

__global__ __launch_bounds__(256)
void hgemm(const float* __restrict__ bias, float* __restrict__ outp, int mode)
{
    extern __shared__ char sm[];
    const uint32_t sb = s2u(sm);
    const int tid = threadIdx.x, lane = tid & 31, wid = tid >> 5;
    const int wm = wid >> 2, wn = wid & 3;          // 2 x 4 warp grid
    const int m0 = blockIdx.y * 128, n0 = blockIdx.x * 128;

    // cp.async plan: 2048 16B chunks / 256 threads
    uint32_t so[8]; const char* gp[8];
    #pragma unroll
    for (int i = 0; i < 8; ++i) {
        int idx = tid + i * 256;
        int t = idx >> 9, r = (idx >> 2) & 127, c = idx & 3;
        so[i] = t * G_TB + r * 80 + c * 16;
        const __nv_bfloat16* src = (t == 0) ? g_xhi : (t == 1) ? g_xlo
                                 : (t == 2) ? g_whi : g_wlo;
        int row = (t < 2) ? (m0 + r) : (n0 + r);
        gp[i] = (const char*)(src + (size_t)row * KDIM) + c * 16;
    }

    const int g = lane >> 3, lo8 = lane & 7;
    const uint32_t aoff = (uint32_t)(wm * 64 + (g & 1) * 8 + lo8) * 80 + (g >> 1) * 16;
    const uint32_t boff = (uint32_t)(wn * 32 + (g >> 1) * 8 + lo8) * 80 + (g & 1) * 16;

    float acc[4][4][4];
    #pragma unroll
    for (int a = 0; a < 4; ++a)
        #pragma unroll
        for (int b = 0; b < 4; ++b)
            #pragma unroll
            for (int c = 0; c < 4; ++c) acc[a][b][c] = 0.f;

    #pragma unroll
    for (int i = 0; i < 8; ++i) cp16(sb + so[i], gp[i]);
    cp_commit();

    for (int ch = 0; ch < 32; ++ch) {
        const uint32_t st = sb + (uint32_t)(ch & 1) * G_STG;
        if (ch < 31) {
            const uint32_t nst = sb + (uint32_t)((ch + 1) & 1) * G_STG;
            const int go = (ch + 1) * 64;
            #pragma unroll
            for (int i = 0; i < 8; ++i) cp16(nst + so[i], gp[i] + go);
            cp_commit();
            cp_wait<1>();
        } else {
            cp_wait<0>();
        }
        __syncthreads();

        #pragma unroll
        for (int ks = 0; ks < 2; ++ks) {
            uint32_t Ah[4][4], Al[4][4], Bh[2][4], Bl[2][4];
            #pragma unroll
            for (int mf = 0; mf < 4; ++mf) {
                ldm4(Ah[mf], st + aoff + mf * 1280 + ks * 32);
                ldm4(Al[mf], st + G_TB + aoff + mf * 1280 + ks * 32);
            }
            #pragma unroll
            for (int n2 = 0; n2 < 2; ++n2) {
                ldm4(Bh[n2], st + 2 * G_TB + boff + n2 * 1280 + ks * 32);
                ldm4(Bl[n2], st + 3 * G_TB + boff + n2 * 1280 + ks * 32);
            }
            #pragma unroll
            for (int mf = 0; mf < 4; ++mf)
                #pragma unroll
                for (int nf = 0; nf < 4; ++nf) {
                    const int n2 = nf >> 1, e = (nf & 1) * 2;
                    mma16816(acc[mf][nf], Ah[mf], Bh[n2][e], Bh[n2][e + 1]);
                    mma16816(acc[mf][nf], Ah[mf], Bl[n2][e], Bl[n2][e + 1]);
                    mma16816(acc[mf][nf], Al[mf], Bh[n2][e], Bh[n2][e + 1]);
                }
        }
        __syncthreads();
    }

    // ---------------- epilogue
    const int r4 = lane >> 2, c2 = (lane & 3) * 2;
    if (mode == 3) {
        #pragma unroll
        for (int mf = 0; mf < 4; ++mf)
            #pragma unroll
            for (int nf = 0; nf < 4; ++nf) {
                const int m = m0 + wm * 64 + mf * 16 + r4;
                const int col = n0 + wn * 32 + nf * 8 + c2;
                const float b0 = bias[col], b1 = bias[col + 1];
                float2 v0 = make_float2(acc[mf][nf][0] + b0, acc[mf][nf][1] + b1);
                float2 v1 = make_float2(acc[mf][nf][2] + b0, acc[mf][nf][3] + b1);
                *(float2*)&outp[(size_t)m * KDIM + col] = v0;
                *(float2*)&outp[(size_t)(m + 8) * KDIM + col] = v1;
            }
    } else {
        __nv_bfloat16* Ch = (mode == 0) ? g_Qh : (mode == 1) ? g_Kh : g_Vh;
        __nv_bfloat16* Cl = (mode == 0) ? g_Ql : (mode == 1) ? g_Kl : g_Vl;
        const float sc = (mode == 0) ? 0.125f : 1.0f;
        #pragma unroll
        for (int mf = 0; mf < 4; ++mf)
            #pragma unroll
            for (int nf = 0; nf < 4; ++nf) {
                const int m = m0 + wm * 64 + mf * 16 + r4;
                const int col = n0 + wn * 32 + nf * 8 + c2;
                const int hh = col >> 6, ss = col & 63;
                const int bb = m >> 11, nn = m & 2047;
                const size_t d0 = (((size_t)(bb * NH + hh)) * NSEQ + nn) * HS + ss;
                uint32_t h, l;
                split2(acc[mf][nf][0] * sc, acc[mf][nf][1] * sc, h, l);
                *(uint32_t*)&Ch[d0] = h; *(uint32_t*)&Cl[d0] = l;
                split2(acc[mf][nf][2] * sc, acc[mf][nf][3] * sc, h, l);
                *(uint32_t*)&Ch[d0 + 8 * HS] = h; *(uint32_t*)&Cl[d0 + 8 * HS] = l;
            }
    }
}

// ---------------------------------------------------------------- attention
// Block: 128 queries (8 warps x 16 rows) of one (b,h); 64-key tiles, online
// softmax, P kept in registers as bf16 hi/lo A-fragments; V via ldmatrix.trans.
// Output written split into g_xhi/g_xlo [b*N][h*64+d] for the final GEMM.
#define A_Q   18432                   // 128 rows * 144B
#define A_KV  9216                    // 64 rows * 144B
#define A_ST  (4*A_KV)                // Kh, Kl, Vh, Vl
#define A_SMEM (2*A_Q + 2*A_ST)       // 110592

__global__ __launch_bounds__(256)
void attn()
{
    extern __shared__ char sm[];
    const uint32_t sb = s2u(sm);
    const uint32_t sQ = sb;
    const uint32_t sKV = sb + 2 * A_Q;
    const int tid = threadIdx.x, lane = tid & 31, w = tid >> 5;
    const int bh = blockIdx.y, i0 = blockIdx.x * 128;
    const size_t base = (size_t)bh * NSEQ * HS;

    // Q load (hi+lo): 2048 chunks
    #pragma unroll
    for (int i = 0; i < 8; ++i) {
        int idx = tid + i * 256;
        int t = idx >> 10, r = (idx >> 3) & 127, c = idx & 7;
        const __nv_bfloat16* src = t ? g_Ql : g_Qh;
        cp16(sQ + t * A_Q + r * 144 + c * 16,
             (const char*)(src + base + (size_t)(i0 + r) * HS) + c * 16);
    }
    cp_commit();

    // KV plan
    uint32_t so[8]; const char* bp[8];
    #pragma unroll
    for (int i = 0; i < 8; ++i) {
        int idx = tid + i * 256;
        int t = idx >> 9, r = (idx >> 3) & 63, c = idx & 7;
        so[i] = t * A_KV + r * 144 + c * 16;
        const __nv_bfloat16* src = (t == 0) ? g_Kh : (t == 1) ? g_Kl
                                 : (t == 2) ? g_Vh : g_Vl;
        bp[i] = (const char*)(src + base + (size_t)r * HS) + c * 16;
    }
    #pragma unroll
    for (int i = 0; i < 8; ++i) cp16(sKV + so[i], bp[i]);   // tile 0 -> stage 0
    cp_commit();

    const int g = lane >> 3, lo8 = lane & 7;
    const uint32_t qoff = (uint32_t)(w * 16 + (g & 1) * 8 + lo8) * 144 + (g >> 1) * 16;
    const uint32_t koff = (uint32_t)((g >> 1) * 8 + lo8) * 144 + (g & 1) * 16;
    const uint32_t voff = (uint32_t)((g & 1) * 8 + lo8) * 144 + (g >> 1) * 16;

    float O[8][4];
    #pragma unroll
    for (int nf = 0; nf < 8; ++nf)
        #pragma unroll
        for (int c = 0; c < 4; ++c) O[nf][c] = 0.f;
    float m2[2] = { -1e30f, -1e30f };
    float l2[2] = { 0.f, 0.f };

    for (int jt = 0; jt < 32; ++jt) {
        const uint32_t st = sKV + (uint32_t)(jt & 1) * A_ST;
        if (jt < 31) {
            const uint32_t nst = sKV + (uint32_t)((jt + 1) & 1) * A_ST;
            const size_t go = (size_t)(jt + 1) * (64 * HS * 2);
            #pragma unroll
            for (int i = 0; i < 8; ++i) cp16(nst + so[i], bp[i] + go);
            cp_commit();
            cp_wait<1>();
        } else {
            cp_wait<0>();
        }
        __syncthreads();

        // ---- S = Q K^T (hi/lo compensated)
        float S[8][4];
        #pragma unroll
        for (int nf = 0; nf < 8; ++nf)
            #pragma unroll
            for (int c = 0; c < 4; ++c) S[nf][c] = 0.f;

        #pragma unroll
        for (int ks = 0; ks < 4; ++ks) {
            uint32_t qh[4], ql[4];
            ldm4(qh, sQ + qoff + ks * 32);
            ldm4(ql, sQ + A_Q + qoff + ks * 32);
            #pragma unroll
            for (int n2 = 0; n2 < 4; ++n2) {
                uint32_t kh[4], kl[4];
                ldm4(kh, st + koff + n2 * 2304 + ks * 32);
                ldm4(kl, st + A_KV + koff + n2 * 2304 + ks * 32);
                #pragma unroll
                for (int e = 0; e < 2; ++e) {
                    float* cc = S[n2 * 2 + e];
                    mma16816(cc, qh, kh[e * 2], kh[e * 2 + 1]);
                    mma16816(cc, qh, kl[e * 2], kl[e * 2 + 1]);
                    mma16816(cc, ql, kh[e * 2], kh[e * 2 + 1]);
                }
            }
        }

        // ---- online softmax (rows r = lane>>2 and r+8; 4 lanes share a row)
        float scl[2];
        #pragma unroll
        for (int j = 0; j < 2; ++j) {
            float mx = -1e30f;
            #pragma unroll
            for (int nf = 0; nf < 8; ++nf)
                mx = fmaxf(mx, fmaxf(S[nf][j * 2], S[nf][j * 2 + 1]));
            mx = fmaxf(mx, __shfl_xor_sync(0xffffffffu, mx, 1));
            mx = fmaxf(mx, __shfl_xor_sync(0xffffffffu, mx, 2));
            const float nm = fmaxf(m2[j], mx);
            scl[j] = __expf(m2[j] - nm);
            m2[j] = nm;
            float rs = 0.f;
            #pragma unroll
            for (int nf = 0; nf < 8; ++nf) {
                float p0 = __expf(S[nf][j * 2] - nm);
                float p1 = __expf(S[nf][j * 2 + 1] - nm);
                S[nf][j * 2] = p0; S[nf][j * 2 + 1] = p1;
                rs += p0 + p1;
            }
            rs += __shfl_xor_sync(0xffffffffu, rs, 1);
            rs += __shfl_xor_sync(0xffffffffu, rs, 2);
            l2[j] = l2[j] * scl[j] + rs;
            #pragma unroll
            for (int nf = 0; nf < 8; ++nf) {
                O[nf][j * 2]     *= scl[j];
                O[nf][j * 2 + 1] *= scl[j];
            }
        }

        // ---- O += P V (P hi/lo in registers, V hi/lo via ldmatrix.trans)
        #pragma unroll
        for (int ks = 0; ks < 4; ++ks) {
            uint32_t ah[4], al[4];
            #pragma unroll
            for (int q = 0; q < 4; ++q) {
                const float* src = S[2 * ks + (q >> 1)];
                const int pr = (q & 1) * 2;
                split2(src[pr], src[pr + 1], ah[q], al[q]);
            }
            #pragma unroll
            for (int n2 = 0; n2 < 4; ++n2) {
                uint32_t vh[4], vl[4];
                ldm4t(vh, st + 2 * A_KV + voff + ks * 2304 + n2 * 32);
                ldm4t(vl, st + 3 * A_KV + voff + ks * 2304 + n2 * 32);
                #pragma unroll
                for (int e = 0; e < 2; ++e) {
                    float* oo = O[n2 * 2 + e];
                    mma16816(oo, ah, vh[e * 2], vh[e * 2 + 1]);
                    mma16816(oo, ah, vl[e * 2], vl[e * 2 + 1]);
                    mma16816(oo, al, vh[e * 2], vh[e * 2 + 1]);
                }
            }
        }
        __syncthreads();
    }

    // ---- finalize: O/l, split to bf16 hi/lo into g_xhi/g_xlo
    const float inv0 = 1.f / l2[0], inv1 = 1.f / l2[1];
    const int bb = bh >> 4, hh = bh & 15;
    const int mr = i0 + w * 16 + (lane >> 2);
    const int col0 = hh * 64 + (lane & 3) * 2;
    #pragma unroll
    for (int nf = 0; nf < 8; ++nf) {
        const int col = col0 + nf * 8;
        uint32_t h, l;
        size_t d0 = (size_t)(bb * NSEQ + mr) * KDIM + col;
        split2(O[nf][0] * inv0, O[nf][1] * inv0, h, l);
        *(uint32_t*)&g_xhi[d0] = h; *(uint32_t*)&g_xlo[d0] = l;
        size_t d1 = d0 + (size_t)8 * KDIM;
        split2(O[nf][2] * inv1, O[nf][3] * inv1, h, l);
        *(uint32_t*)&g_xhi[d1] = h; *(uint32_t*)&g_xlo[d1] = l;
    }
}

// ---------------------------------------------------------------- launch
extern "C" void kernel_launch(void* const* d_in, const int* in_sizes, int n_in,
                              void* d_out, int out_size)
{
    (void)in_sizes; (void)n_in; (void)out_size;
    // metadata order: x, Wk, Wq, Wv, Wu, bu
    const float* x  = (const float*)d_in[0];
    const float* Wk = (const float*)d_in[1];
    const float* Wq = (const float*)d_in[2];
    const float* Wv = (const float*)d_in[3];
    const float* Wu = (const float*)d_in[4];
    const float* bu = (const float*)d_in[5];
    float* out = (float*)d_out;

    cudaFuncSetAttribute(hgemm, cudaFuncAttributeMaxDynamicSharedMemorySize, G_SMEM);
    cudaFuncSetAttribute(attn,  cudaFuncAttributeMaxDynamicSharedMemorySize, A_SMEM);

    const dim3 ggrid(KDIM / 128, MROWS / 128);        // (8, 64)
    const int XBLK = (MROWS * KDIM) / (4 * 256);      // 8192
    const int WBLK = (KDIM * KDIM) / (4 * 256);       // 1024

    cvt<<<XBLK, 256>>>(x, 0);                         // x -> g_xhi/g_xlo
    cvt<<<WBLK, 256>>>(Wq, 1);
    hgemm<<<ggrid, 256, G_SMEM>>>(nullptr, nullptr, 0);   // -> Qh/Ql (scaled)
    cvt<<<WBLK, 256>>>(Wk, 1);
    hgemm<<<ggrid, 256, G_SMEM>>>(nullptr, nullptr, 1);   // -> Kh/Kl
    cvt<<<WBLK, 256>>>(Wv, 1);
    hgemm<<<ggrid, 256, G_SMEM>>>(nullptr, nullptr, 2);   // -> Vh/Vl

    attn<<<dim3(NSEQ / 128, BSZ * NH), 256, A_SMEM>>>();  // -> g_xhi/g_xlo

    cvt<<<WBLK, 256>>>(Wu, 1);
    hgemm<<<ggrid, 256, G_SMEM>>>(bu, out, 3);            // -> d_out + bias
}

// round 9
// speedup vs baseline: 3.4519x; 1.0001x over previous
#include <cuda_runtime.h>
#include <cuda_bf16.h>
#include <cstdint>
#include <cstddef>

// ---------------------------------------------------------------- constants
#define BSZ   4
#define NSEQ  2048
#define KDIM  1024
#define NH    16
#define HS    64
#define MROWS (BSZ*NSEQ)              // 8192
#define QKVN  (BSZ*NH*NSEQ*HS)        // 8388608

// ---------------------------------------------------------------- scratch
__device__ __align__(16) __nv_bfloat16 g_xhi[MROWS*KDIM];
__device__ __align__(16) __nv_bfloat16 g_xlo[MROWS*KDIM];
__device__ __align__(16) __nv_bfloat16 g_whi[3*KDIM*KDIM];   // packed Wq|Wk|Wv (or Wu in [0])
__device__ __align__(16) __nv_bfloat16 g_wlo[3*KDIM*KDIM];
__device__ __align__(16) __nv_bfloat16 g_Qh[QKVN], g_Ql[QKVN];
__device__ __align__(16) __nv_bfloat16 g_Kh[QKVN], g_Kl[QKVN];
__device__ __align__(16) __nv_bfloat16 g_Vh[QKVN], g_Vl[QKVN];

// ---------------------------------------------------------------- helpers
__device__ __forceinline__ uint32_t s2u(const void* p) {
    uint32_t a;
    asm("{ .reg .u64 t; cvta.to.shared.u64 t, %1; cvt.u32.u64 %0, t; }" : "=r"(a) : "l"(p));
    return a;
}
__device__ __forceinline__ void cp16(uint32_t dst, const void* src) {
    asm volatile("cp.async.cg.shared.global [%0], [%1], 16;" :: "r"(dst), "l"(src) : "memory");
}
__device__ __forceinline__ void cp_commit() {
    asm volatile("cp.async.commit_group;" ::: "memory");
}
template<int N> __device__ __forceinline__ void cp_wait() {
    asm volatile("cp.async.wait_group %0;" :: "n"(N) : "memory");
}
__device__ __forceinline__ void ldm4(uint32_t* r, uint32_t a) {
    asm volatile("ldmatrix.sync.aligned.m8n8.x4.shared.b16 {%0,%1,%2,%3}, [%4];"
        : "=r"(r[0]), "=r"(r[1]), "=r"(r[2]), "=r"(r[3]) : "r"(a));
}
__device__ __forceinline__ void ldm4t(uint32_t* r, uint32_t a) {
    asm volatile("ldmatrix.sync.aligned.m8n8.x4.trans.shared.b16 {%0,%1,%2,%3}, [%4];"
        : "=r"(r[0]), "=r"(r[1]), "=r"(r[2]), "=r"(r[3]) : "r"(a));
}
__device__ __forceinline__ void mma16816(float* c, const uint32_t* a, uint32_t b0, uint32_t b1) {
    asm volatile("mma.sync.aligned.m16n8k16.row.col.f32.bf16.bf16.f32 "
        "{%0,%1,%2,%3}, {%4,%5,%6,%7}, {%8,%9}, {%0,%1,%2,%3};"
        : "+f"(c[0]), "+f"(c[1]), "+f"(c[2]), "+f"(c[3])
        : "r"(a[0]), "r"(a[1]), "r"(a[2]), "r"(a[3]), "r"(b0), "r"(b1));
}
__device__ __forceinline__ uint32_t pack2(float f0, float f1) {
    uint32_t r; asm("cvt.rn.bf16x2.f32 %0, %1, %2;" : "=r"(r) : "f"(f1), "f"(f0)); return r;
}
__device__ __forceinline__ float lo2f(uint32_t p) { return __uint_as_float(p << 16); }
__device__ __forceinline__ float hi2f(uint32_t p) { return __uint_as_float(p & 0xffff0000u); }
__device__ __forceinline__ void split2(float f0, float f1, uint32_t& h, uint32_t& l) {
    h = pack2(f0, f1);
    l = pack2(f0 - lo2f(h), f1 - hi2f(h));
}

// ---------------------------------------------------------------- converts
// x -> g_xhi/g_xlo
__global__ __launch_bounds__(256) void cvt_x(const float* __restrict__ src)
{
    size_t i = ((size_t)blockIdx.x * 256 + threadIdx.x) * 4;
    float4 v = *(const float4*)(src + i);
    uint32_t h0, l0, h1, l1;
    split2(v.x, v.y, h0, l0);
    split2(v.z, v.w, h1, l1);
    *(uint2*)(g_xhi + i) = make_uint2(h0, h1);
    *(uint2*)(g_xlo + i) = make_uint2(l0, l1);
}
// up to 3 weight matrices -> packed g_whi/g_wlo rows [0,3072)
#define WBLK ((KDIM*KDIM)/(4*256))    // 1024 blocks per matrix
__global__ __launch_bounds__(256) void cvt_w(const float* __restrict__ w0,
                                             const float* __restrict__ w1,
                                             const float* __restrict__ w2)
{
    const int sel = blockIdx.x / WBLK;
    const float* src = (sel == 0) ? w0 : (sel == 1) ? w1 : w2;
    size_t li = ((size_t)(blockIdx.x % WBLK) * 256 + threadIdx.x) * 4;
    size_t i = (size_t)sel * (KDIM * KDIM) + li;
    float4 v = *(const float4*)(src + li);
    uint32_t h0, l0, h1, l1;
    split2(v.x, v.y, h0, l0);
    split2(v.z, v.w, h1, l1);
    *(uint2*)(g_whi + i) = make_uint2(h0, h1);
    *(uint2*)(g_wlo + i) = make_uint2(l0, l1);
}

// ---------------------------------------------------------------- HMMA GEMM
// C[m][n] = sum_k A[m][k]*Wpacked[n][k], hi/lo compensated (3 MMA products).
// mode 0: n in [0,3072) -> split-write g_{Q,K,V}{h,l} [b][h][n][s] (Q x0.125)
// mode 3: n in [0,1024) -> outp[m][n] = C + bias[n] (fp32)
#define G_TB   10240                  // 128 rows * 80B (64B data + 16B pad)
#define G_STG  (4*G_TB)               // Ahi, Alo, Bhi, Blo = 40960
#define G_NST  3
#define G_SMEM (G_NST*G_STG)          // 122880
#define G_CH   32                     // K chunks of 32

__global__ __launch_bounds__(256)
void hgemm(const float* __restrict__ bias, float* __restrict__ outp, int mode)
{
    extern __shared__ char sm[];
    const uint32_t sb = s2u(sm);
    const int tid = threadIdx.x, lane = tid & 31, wid = tid >> 5;
    const int wm = wid >> 2, wn = wid & 3;          // 2 x 4 warp grid
    const int m0 = blockIdx.y * 128, n0 = blockIdx.x * 128;

    // cp.async plan: 2048 16B chunks / 256 threads
    uint32_t so[8]; const char* gp[8];
    #pragma unroll
    for (int i = 0; i < 8; ++i) {
        int idx = tid + i * 256;
        int t = idx >> 9, r = (idx >> 2) & 127, c = idx & 3;
        so[i] = t * G_TB + r * 80 + c * 16;
        const __nv_bfloat16* src = (t == 0) ? g_xhi : (t == 1) ? g_xlo
                                 : (t == 2) ? g_whi : g_wlo;
        int row = (t < 2) ? (m0 + r) : (n0 + r);
        gp[i] = (const char*)(src + (size_t)row * KDIM) + c * 16;
    }

    const int g = lane >> 3, lo8 = lane & 7;
    const uint32_t aoff = (uint32_t)(wm * 64 + (g & 1) * 8 + lo8) * 80 + (g >> 1) * 16;
    const uint32_t boff = (uint32_t)(wn * 32 + (g >> 1) * 8 + lo8) * 80 + (g & 1) * 16;

    float acc[4][4][4];
    #pragma unroll
    for (int a = 0; a < 4; ++a)
        #pragma unroll
        for (int b = 0; b < 4; ++b)
            #pragma unroll
            for (int c = 0; c < 4; ++c) acc[a][b][c] = 0.f;

    // prologue: stages 0 and 1
    #pragma unroll
    for (int i = 0; i < 8; ++i) cp16(sb + so[i], gp[i]);
    cp_commit();
    #pragma unroll
    for (int i = 0; i < 8; ++i) cp16(sb + G_STG + so[i], gp[i] + 64);
    cp_commit();

    int stg = 0;                     // = ch % 3
    for (int ch = 0; ch < G_CH; ++ch) {
        if (ch < G_CH - 1) cp_wait<1>(); else cp_wait<0>();
        __syncthreads();
        if (ch + 2 < G_CH) {
            int ps = stg + 2; if (ps >= 3) ps -= 3;
            const uint32_t nst = sb + (uint32_t)ps * G_STG;
            const int go = (ch + 2) * 64;
            #pragma unroll
            for (int i = 0; i < 8; ++i) cp16(nst + so[i], gp[i] + go);
            cp_commit();
        }

        const uint32_t st = sb + (uint32_t)stg * G_STG;
        #pragma unroll
        for (int ks = 0; ks < 2; ++ks) {
            uint32_t Ah[4][4], Al[4][4], Bh[2][4], Bl[2][4];
            #pragma unroll
            for (int mf = 0; mf < 4; ++mf) {
                ldm4(Ah[mf], st + aoff + mf * 1280 + ks * 32);
                ldm4(Al[mf], st + G_TB + aoff + mf * 1280 + ks * 32);
            }
            #pragma unroll
            for (int n2 = 0; n2 < 2; ++n2) {
                ldm4(Bh[n2], st + 2 * G_TB + boff + n2 * 1280 + ks * 32);
                ldm4(Bl[n2], st + 3 * G_TB + boff + n2 * 1280 + ks * 32);
            }
            #pragma unroll
            for (int mf = 0; mf < 4; ++mf)
                #pragma unroll
                for (int nf = 0; nf < 4; ++nf) {
                    const int n2 = nf >> 1, e = (nf & 1) * 2;
                    mma16816(acc[mf][nf], Ah[mf], Bh[n2][e], Bh[n2][e + 1]);
                    mma16816(acc[mf][nf], Ah[mf], Bl[n2][e], Bl[n2][e + 1]);
                    mma16816(acc[mf][nf], Al[mf], Bh[n2][e], Bh[n2][e + 1]);
                }
        }
        if (++stg == 3) stg = 0;
    }

    // ---------------- epilogue
    const int r4 = lane >> 2, c2 = (lane & 3) * 2;
    if (mode == 3) {
        #pragma unroll
        for (int mf = 0; mf < 4; ++mf)
            #pragma unroll
            for (int nf = 0; nf < 4; ++nf) {
                const int m = m0 + wm * 64 + mf * 16 + r4;
                const int col = n0 + wn * 32 + nf * 8 + c2;
                const float b0 = bias[col], b1 = bias[col + 1];
                float2 v0 = make_float2(acc[mf][nf][0] + b0, acc[mf][nf][1] + b1);
                float2 v1 = make_float2(acc[mf][nf][2] + b0, acc[mf][nf][3] + b1);
                *(float2*)&outp[(size_t)m * KDIM + col] = v0;
                *(float2*)&outp[(size_t)(m + 8) * KDIM + col] = v1;
            }
    } else {
        const int mat = n0 >> 10;                 // 0=Q 1=K 2=V (block-constant)
        __nv_bfloat16* Ch = (mat == 0) ? g_Qh : (mat == 1) ? g_Kh : g_Vh;
        __nv_bfloat16* Cl = (mat == 0) ? g_Ql : (mat == 1) ? g_Kl : g_Vl;
        const float sc = (mat == 0) ? 0.125f : 1.0f;
        #pragma unroll
        for (int mf = 0; mf < 4; ++mf)
            #pragma unroll
            for (int nf = 0; nf < 4; ++nf) {
                const int m = m0 + wm * 64 + mf * 16 + r4;
                const int col = (n0 & 1023) + wn * 32 + nf * 8 + c2;
                const int hh = col >> 6, ss = col & 63;
                const int bb = m >> 11, nn = m & 2047;
                const size_t d0 = (((size_t)(bb * NH + hh)) * NSEQ + nn) * HS + ss;
                uint32_t h, l;
                split2(acc[mf][nf][0] * sc, acc[mf][nf][1] * sc, h, l);
                *(uint32_t*)&Ch[d0] = h; *(uint32_t*)&Cl[d0] = l;
                split2(acc[mf][nf][2] * sc, acc[mf][nf][3] * sc, h, l);
                *(uint32_t*)&Ch[d0 + 8 * HS] = h; *(uint32_t*)&Cl[d0 + 8 * HS] = l;
            }
    }
}

// ---------------------------------------------------------------- attention
// Block: 128 queries (8 warps x 16 rows) of one (b,h); 64-key tiles, online
// softmax, P as bf16 hi/lo A-frags in registers; V via ldmatrix.trans.
// 3-stage KV pipeline. Output split into g_xhi/g_xlo for the final GEMM.
#define A_Q   18432                   // 128 rows * 144B
#define A_KV  9216                    // 64 rows * 144B
#define A_ST  (4*A_KV)                // Kh, Kl, Vh, Vl = 36864
#define A_NST 3
#define A_SMEM (2*A_Q + A_NST*A_ST)   // 147456
#define A_TI  (NSEQ/64)               // 32 key tiles

__global__ __launch_bounds__(256)
void attn()
{
    extern __shared__ char sm[];
    const uint32_t sb = s2u(sm);
    const uint32_t sQ = sb;
    const uint32_t sKV = sb + 2 * A_Q;
    const int tid = threadIdx.x, lane = tid & 31, w = tid >> 5;
    const int bh = blockIdx.y, i0 = blockIdx.x * 128;
    const size_t base = (size_t)bh * NSEQ * HS;

    // Q load (hi+lo)
    #pragma unroll
    for (int i = 0; i < 8; ++i) {
        int idx = tid + i * 256;
        int t = idx >> 10, r = (idx >> 3) & 127, c = idx & 7;
        const __nv_bfloat16* src = t ? g_Ql : g_Qh;
        cp16(sQ + t * A_Q + r * 144 + c * 16,
             (const char*)(src + base + (size_t)(i0 + r) * HS) + c * 16);
    }

    // KV plan
    uint32_t so[8]; const char* bp[8];
    #pragma unroll
    for (int i = 0; i < 8; ++i) {
        int idx = tid + i * 256;
        int t = idx >> 9, r = (idx >> 3) & 63, c = idx & 7;
        so[i] = t * A_KV + r * 144 + c * 16;
        const __nv_bfloat16* src = (t == 0) ? g_Kh : (t == 1) ? g_Kl
                                 : (t == 2) ? g_Vh : g_Vl;
        bp[i] = (const char*)(src + base + (size_t)r * HS) + c * 16;
    }
    // prologue: Q + KV tile 0 in one group; KV tile 1 in a second
    #pragma unroll
    for (int i = 0; i < 8; ++i) cp16(sKV + so[i], bp[i]);
    cp_commit();
    #pragma unroll
    for (int i = 0; i < 8; ++i) cp16(sKV + A_ST + so[i], bp[i] + 64 * HS * 2);
    cp_commit();

    const int g = lane >> 3, lo8 = lane & 7;
    const uint32_t qoff = (uint32_t)(w * 16 + (g & 1) * 8 + lo8) * 144 + (g >> 1) * 16;
    const uint32_t koff = (uint32_t)((g >> 1) * 8 + lo8) * 144 + (g & 1) * 16;
    const uint32_t voff = (uint32_t)((g & 1) * 8 + lo8) * 144 + (g >> 1) * 16;

    float O[8][4];
    #pragma unroll
    for (int nf = 0; nf < 8; ++nf)
        #pragma unroll
        for (int c = 0; c < 4; ++c) O[nf][c] = 0.f;
    float m2[2] = { -1e30f, -1e30f };
    float l2[2] = { 0.f, 0.f };

    int stg = 0;
    for (int jt = 0; jt < A_TI; ++jt) {
        if (jt < A_TI - 1) cp_wait<1>(); else cp_wait<0>();
        __syncthreads();
        if (jt + 2 < A_TI) {
            int ps = stg + 2; if (ps >= 3) ps -= 3;
            const uint32_t nst = sKV + (uint32_t)ps * A_ST;
            const size_t go = (size_t)(jt + 2) * (64 * HS * 2);
            #pragma unroll
            for (int i = 0; i < 8; ++i) cp16(nst + so[i], bp[i] + go);
            cp_commit();
        }
        const uint32_t st = sKV + (uint32_t)stg * A_ST;

        // ---- S = Q K^T (hi/lo compensated)
        float S[8][4];
        #pragma unroll
        for (int nf = 0; nf < 8; ++nf)
            #pragma unroll
            for (int c = 0; c < 4; ++c) S[nf][c] = 0.f;

        #pragma unroll
        for (int ks = 0; ks < 4; ++ks) {
            uint32_t qh[4], ql[4];
            ldm4(qh, sQ + qoff + ks * 32);
            ldm4(ql, sQ + A_Q + qoff + ks * 32);
            #pragma unroll
            for (int n2 = 0; n2 < 4; ++n2) {
                uint32_t kh[4], kl[4];
                ldm4(kh, st + koff + n2 * 2304 + ks * 32);
                ldm4(kl, st + A_KV + koff + n2 * 2304 + ks * 32);
                #pragma unroll
                for (int e = 0; e < 2; ++e) {
                    float* cc = S[n2 * 2 + e];
                    mma16816(cc, qh, kh[e * 2], kh[e * 2 + 1]);
                    mma16816(cc, qh, kl[e * 2], kl[e * 2 + 1]);
                    mma16816(cc, ql, kh[e * 2], kh[e * 2 + 1]);
                }
            }
        }

        // ---- online softmax
        float scl[2];
        #pragma unroll
        for (int j = 0; j < 2; ++j) {
            float mx = -1e30f;
            #pragma unroll
            for (int nf = 0; nf < 8; ++nf)
                mx = fmaxf(mx, fmaxf(S[nf][j * 2], S[nf][j * 2 + 1]));
            mx = fmaxf(mx, __shfl_xor_sync(0xffffffffu, mx, 1));
            mx = fmaxf(mx, __shfl_xor_sync(0xffffffffu, mx, 2));
            const float nm = fmaxf(m2[j], mx);
            scl[j] = __expf(m2[j] - nm);
            m2[j] = nm;
            float rs = 0.f;
            #pragma unroll
            for (int nf = 0; nf < 8; ++nf) {
                float p0 = __expf(S[nf][j * 2] - nm);
                float p1 = __expf(S[nf][j * 2 + 1] - nm);
                S[nf][j * 2] = p0; S[nf][j * 2 + 1] = p1;
                rs += p0 + p1;
            }
            rs += __shfl_xor_sync(0xffffffffu, rs, 1);
            rs += __shfl_xor_sync(0xffffffffu, rs, 2);
            l2[j] = l2[j] * scl[j] + rs;
            #pragma unroll
            for (int nf = 0; nf < 8; ++nf) {
                O[nf][j * 2]     *= scl[j];
                O[nf][j * 2 + 1] *= scl[j];
            }
        }

        // ---- O += P V
        #pragma unroll
        for (int ks = 0; ks < 4; ++ks) {
            uint32_t ah[4], al[4];
            #pragma unroll
            for (int q = 0; q < 4; ++q) {
                const float* src = S[2 * ks + (q >> 1)];
                const int pr = (q & 1) * 2;
                split2(src[pr], src[pr + 1], ah[q], al[q]);
            }
            #pragma unroll
            for (int n2 = 0; n2 < 4; ++n2) {
                uint32_t vh[4], vl[4];
                ldm4t(vh, st + 2 * A_KV + voff + ks * 2304 + n2 * 32);
                ldm4t(vl, st + 3 * A_KV + voff + ks * 2304 + n2 * 32);
                #pragma unroll
                for (int e = 0; e < 2; ++e) {
                    float* oo = O[n2 * 2 + e];
                    mma16816(oo, ah, vh[e * 2], vh[e * 2 + 1]);
                    mma16816(oo, ah, vl[e * 2], vl[e * 2 + 1]);
                    mma16816(oo, al, vh[e * 2], vh[e * 2 + 1]);
                }
            }
        }
        if (++stg == 3) stg = 0;
    }

    // ---- finalize
    const float inv0 = 1.f / l2[0], inv1 = 1.f / l2[1];
    const int bb = bh >> 4, hh = bh & 15;
    const int mr = i0 + w * 16 + (lane >> 2);
    const int col0 = hh * 64 + (lane & 3) * 2;
    #pragma unroll
    for (int nf = 0; nf < 8; ++nf) {
        const int col = col0 + nf * 8;
        uint32_t h, l;
        size_t d0 = (size_t)(bb * NSEQ + mr) * KDIM + col;
        split2(O[nf][0] * inv0, O[nf][1] * inv0, h, l);
        *(uint32_t*)&g_xhi[d0] = h; *(uint32_t*)&g_xlo[d0] = l;
        size_t d1 = d0 + (size_t)8 * KDIM;
        split2(O[nf][2] * inv1, O[nf][3] * inv1, h, l);
        *(uint32_t*)&g_xhi[d1] = h; *(uint32_t*)&g_xlo[d1] = l;
    }
}

// ---------------------------------------------------------------- launch
extern "C" void kernel_launch(void* const* d_in, const int* in_sizes, int n_in,
                              void* d_out, int out_size)
{
    (void)in_sizes; (void)n_in; (void)out_size;
    // metadata order: x, Wk, Wq, Wv, Wu, bu
    const float* x  = (const float*)d_in[0];
    const float* Wk = (const float*)d_in[1];
    const float* Wq = (const float*)d_in[2];
    const float* Wv = (const float*)d_in[3];
    const float* Wu = (const float*)d_in[4];
    const float* bu = (const float*)d_in[5];
    float* out = (float*)d_out;

    cudaFuncSetAttribute(hgemm, cudaFuncAttributeMaxDynamicSharedMemorySize, G_SMEM);
    cudaFuncSetAttribute(attn,  cudaFuncAttributeMaxDynamicSharedMemorySize, A_SMEM);

    const int XBLK = (MROWS * KDIM) / (4 * 256);          // 8192

    cvt_x<<<XBLK, 256>>>(x);                              // x -> hi/lo
    cvt_w<<<3 * WBLK, 256>>>(Wq, Wk, Wv);                 // packed weights
    hgemm<<<dim3(3 * KDIM / 128, MROWS / 128), 256, G_SMEM>>>(nullptr, nullptr, 0); // QKV
    attn<<<dim3(NSEQ / 128, BSZ * NH), 256, A_SMEM>>>();  // -> g_xhi/g_xlo
    cvt_w<<<WBLK, 256>>>(Wu, Wu, Wu);                     // Wu -> rows [0,1024)
    hgemm<<<dim3(KDIM / 128, MROWS / 128), 256, G_SMEM>>>(bu, out, 3);  // out
}

// round 11
// speedup vs baseline: 3.9574x; 1.1464x over previous
#include <cuda_runtime.h>
#include <cuda_bf16.h>
#include <cstdint>
#include <cstddef>

// ---------------------------------------------------------------- constants
#define BSZ   4
#define NSEQ  2048
#define KDIM  1024
#define NH    16
#define HS    64
#define MROWS (BSZ*NSEQ)              // 8192
#define QKVN  (BSZ*NH*NSEQ*HS)        // 8388608

// ---------------------------------------------------------------- scratch
__device__ __align__(16) __nv_bfloat16 g_xhi[MROWS*KDIM];
__device__ __align__(16) __nv_bfloat16 g_xlo[MROWS*KDIM];
__device__ __align__(16) __nv_bfloat16 g_whi[3*KDIM*KDIM];   // packed Wq|Wk|Wv (or Wu in [0])
__device__ __align__(16) __nv_bfloat16 g_wlo[3*KDIM*KDIM];
__device__ __align__(16) __nv_bfloat16 g_Qh[QKVN], g_Ql[QKVN];
__device__ __align__(16) __nv_bfloat16 g_Kh[QKVN], g_Kl[QKVN];
__device__ __align__(16) __nv_bfloat16 g_Vh[QKVN], g_Vl[QKVN];

// ---------------------------------------------------------------- helpers
__device__ __forceinline__ uint32_t s2u(const void* p) {
    uint32_t a;
    asm("{ .reg .u64 t; cvta.to.shared.u64 t, %1; cvt.u32.u64 %0, t; }" : "=r"(a) : "l"(p));
    return a;
}
__device__ __forceinline__ void cp16(uint32_t dst, const void* src) {
    asm volatile("cp.async.cg.shared.global [%0], [%1], 16;" :: "r"(dst), "l"(src) : "memory");
}
__device__ __forceinline__ void cp_commit() {
    asm volatile("cp.async.commit_group;" ::: "memory");
}
template<int N> __device__ __forceinline__ void cp_wait() {
    asm volatile("cp.async.wait_group %0;" :: "n"(N) : "memory");
}
__device__ __forceinline__ void ldm4(uint32_t* r, uint32_t a) {
    asm volatile("ldmatrix.sync.aligned.m8n8.x4.shared.b16 {%0,%1,%2,%3}, [%4];"
        : "=r"(r[0]), "=r"(r[1]), "=r"(r[2]), "=r"(r[3]) : "r"(a));
}
__device__ __forceinline__ void ldm4t(uint32_t* r, uint32_t a) {
    asm volatile("ldmatrix.sync.aligned.m8n8.x4.trans.shared.b16 {%0,%1,%2,%3}, [%4];"
        : "=r"(r[0]), "=r"(r[1]), "=r"(r[2]), "=r"(r[3]) : "r"(a));
}
__device__ __forceinline__ void mma16816(float* c, const uint32_t* a, uint32_t b0, uint32_t b1) {
    asm volatile("mma.sync.aligned.m16n8k16.row.col.f32.bf16.bf16.f32 "
        "{%0,%1,%2,%3}, {%4,%5,%6,%7}, {%8,%9}, {%0,%1,%2,%3};"
        : "+f"(c[0]), "+f"(c[1]), "+f"(c[2]), "+f"(c[3])
        : "r"(a[0]), "r"(a[1]), "r"(a[2]), "r"(a[3]), "r"(b0), "r"(b1));
}
__device__ __forceinline__ uint32_t pack2(float f0, float f1) {
    uint32_t r; asm("cvt.rn.bf16x2.f32 %0, %1, %2;" : "=r"(r) : "f"(f1), "f"(f0)); return r;
}
__device__ __forceinline__ float lo2f(uint32_t p) { return __uint_as_float(p << 16); }
__device__ __forceinline__ float hi2f(uint32_t p) { return __uint_as_float(p & 0xffff0000u); }
__device__ __forceinline__ void split2(float f0, float f1, uint32_t& h, uint32_t& l) {
    h = pack2(f0, f1);
    l = pack2(f0 - lo2f(h), f1 - hi2f(h));
}

// ---------------------------------------------------------------- converts
__global__ __launch_bounds__(256) void cvt_x(const float* __restrict__ src)
{
    size_t i = ((size_t)blockIdx.x * 256 + threadIdx.x) * 4;
    float4 v = *(const float4*)(src + i);
    uint32_t h0, l0, h1, l1;
    split2(v.x, v.y, h0, l0);
    split2(v.z, v.w, h1, l1);
    *(uint2*)(g_xhi + i) = make_uint2(h0, h1);
    *(uint2*)(g_xlo + i) = make_uint2(l0, l1);
}
#define WBLK ((KDIM*KDIM)/(4*256))    // 1024 blocks per matrix
__global__ __launch_bounds__(256) void cvt_w(const float* __restrict__ w0,
                                             const float* __restrict__ w1,
                                             const float* __restrict__ w2)
{
    const int sel = blockIdx.x / WBLK;
    const float* src = (sel == 0) ? w0 : (sel == 1) ? w1 : w2;
    size_t li = ((size_t)(blockIdx.x % WBLK) * 256 + threadIdx.x) * 4;
    size_t i = (size_t)sel * (KDIM * KDIM) + li;
    float4 v = *(const float4*)(src + li);
    uint32_t h0, l0, h1, l1;
    split2(v.x, v.y, h0, l0);
    split2(v.z, v.w, h1, l1);
    *(uint2*)(g_whi + i) = make_uint2(h0, h1);
    *(uint2*)(g_wlo + i) = make_uint2(l0, l1);
}

// ---------------------------------------------------------------- HMMA GEMM
// C[m][n] = sum_k A[m][k]*Wpacked[n][k], hi/lo compensated (3 MMA products).
// mode 0: n in [0,3072) -> split-write g_{Q,K,V}{h,l} [b][h][n][s] (Q x0.125)
// mode 3: n in [0,1024) -> outp[m][n] = C + bias[n] (fp32)
#define G_TB   10240                  // 128 rows * 80B (64B data + 16B pad)
#define G_STG  (4*G_TB)               // Ahi, Alo, Bhi, Blo = 40960
#define G_SMEM (2*G_STG)              // 81920 -> 2 CTAs/SM
#define G_CH   32                     // K chunks of 32

__global__ __launch_bounds__(256, 2)
void hgemm(const float* __restrict__ bias, float* __restrict__ outp, int mode)
{
    extern __shared__ char sm[];
    const uint32_t sb = s2u(sm);
    const int tid = threadIdx.x, lane = tid & 31, wid = tid >> 5;
    const int wm = wid >> 2, wn = wid & 3;          // 2 x 4 warp grid
    const int m0 = blockIdx.y * 128, n0 = blockIdx.x * 128;

    // cp.async plan: 2048 16B chunks / 256 threads
    uint32_t so[8]; const char* gp[8];
    #pragma unroll
    for (int i = 0; i < 8; ++i) {
        int idx = tid + i * 256;
        int t = idx >> 9, r = (idx >> 2) & 127, c = idx & 3;
        so[i] = t * G_TB + r * 80 + c * 16;
        const __nv_bfloat16* src = (t == 0) ? g_xhi : (t == 1) ? g_xlo
                                 : (t == 2) ? g_whi : g_wlo;
        int row = (t < 2) ? (m0 + r) : (n0 + r);
        gp[i] = (const char*)(src + (size_t)row * KDIM) + c * 16;
    }

    const int g = lane >> 3, lo8 = lane & 7;
    const uint32_t aoff = (uint32_t)(wm * 64 + (g & 1) * 8 + lo8) * 80 + (g >> 1) * 16;
    const uint32_t boff = (uint32_t)(wn * 32 + (g >> 1) * 8 + lo8) * 80 + (g & 1) * 16;

    float acc[4][4][4];
    #pragma unroll
    for (int a = 0; a < 4; ++a)
        #pragma unroll
        for (int b = 0; b < 4; ++b)
            #pragma unroll
            for (int c = 0; c < 4; ++c) acc[a][b][c] = 0.f;

    // prologue: tile 0 -> stage 0
    #pragma unroll
    for (int i = 0; i < 8; ++i) cp16(sb + so[i], gp[i]);
    cp_commit();

    for (int ch = 0; ch < G_CH; ++ch) {
        const uint32_t st = sb + (uint32_t)(ch & 1) * G_STG;
        // barrier 1: every warp finished reading buffer (ch+1)&1 (iter ch-1)
        __syncthreads();
        if (ch + 1 < G_CH) {
            const uint32_t nst = sb + (uint32_t)((ch + 1) & 1) * G_STG;
            const int go = (ch + 1) * 64;
            #pragma unroll
            for (int i = 0; i < 8; ++i) cp16(nst + so[i], gp[i] + go);
            cp_commit();
            cp_wait<1>();          // tile ch landed (tile ch+1 in flight)
        } else {
            cp_wait<0>();
        }
        // barrier 2: tile ch visible to all warps
        __syncthreads();

        #pragma unroll
        for (int ks = 0; ks < 2; ++ks) {
            uint32_t Ah[4][4], Al[4][4], Bh[2][4], Bl[2][4];
            #pragma unroll
            for (int mf = 0; mf < 4; ++mf) {
                ldm4(Ah[mf], st + aoff + mf * 1280 + ks * 32);
                ldm4(Al[mf], st + G_TB + aoff + mf * 1280 + ks * 32);
            }
            #pragma unroll
            for (int n2 = 0; n2 < 2; ++n2) {
                ldm4(Bh[n2], st + 2 * G_TB + boff + n2 * 1280 + ks * 32);
                ldm4(Bl[n2], st + 3 * G_TB + boff + n2 * 1280 + ks * 32);
            }
            #pragma unroll
            for (int mf = 0; mf < 4; ++mf)
                #pragma unroll
                for (int nf = 0; nf < 4; ++nf) {
                    const int n2 = nf >> 1, e = (nf & 1) * 2;
                    mma16816(acc[mf][nf], Ah[mf], Bh[n2][e], Bh[n2][e + 1]);
                    mma16816(acc[mf][nf], Ah[mf], Bl[n2][e], Bl[n2][e + 1]);
                    mma16816(acc[mf][nf], Al[mf], Bh[n2][e], Bh[n2][e + 1]);
                }
        }
    }

    // ---------------- epilogue
    const int r4 = lane >> 2, c2 = (lane & 3) * 2;
    if (mode == 3) {
        #pragma unroll
        for (int mf = 0; mf < 4; ++mf)
            #pragma unroll
            for (int nf = 0; nf < 4; ++nf) {
                const int m = m0 + wm * 64 + mf * 16 + r4;
                const int col = n0 + wn * 32 + nf * 8 + c2;
                const float b0 = bias[col], b1 = bias[col + 1];
                float2 v0 = make_float2(acc[mf][nf][0] + b0, acc[mf][nf][1] + b1);
                float2 v1 = make_float2(acc[mf][nf][2] + b0, acc[mf][nf][3] + b1);
                *(float2*)&outp[(size_t)m * KDIM + col] = v0;
                *(float2*)&outp[(size_t)(m + 8) * KDIM + col] = v1;
            }
    } else {
        const int mat = n0 >> 10;                 // 0=Q 1=K 2=V (block-constant)
        __nv_bfloat16* Ch = (mat == 0) ? g_Qh : (mat == 1) ? g_Kh : g_Vh;
        __nv_bfloat16* Cl = (mat == 0) ? g_Ql : (mat == 1) ? g_Kl : g_Vl;
        const float sc = (mat == 0) ? 0.125f : 1.0f;
        #pragma unroll
        for (int mf = 0; mf < 4; ++mf)
            #pragma unroll
            for (int nf = 0; nf < 4; ++nf) {
                const int m = m0 + wm * 64 + mf * 16 + r4;
                const int col = (n0 & 1023) + wn * 32 + nf * 8 + c2;
                const int hh = col >> 6, ss = col & 63;
                const int bb = m >> 11, nn = m & 2047;
                const size_t d0 = (((size_t)(bb * NH + hh)) * NSEQ + nn) * HS + ss;
                uint32_t h, l;
                split2(acc[mf][nf][0] * sc, acc[mf][nf][1] * sc, h, l);
                *(uint32_t*)&Ch[d0] = h; *(uint32_t*)&Cl[d0] = l;
                split2(acc[mf][nf][2] * sc, acc[mf][nf][3] * sc, h, l);
                *(uint32_t*)&Ch[d0 + 8 * HS] = h; *(uint32_t*)&Cl[d0 + 8 * HS] = l;
            }
    }
}

// ---------------------------------------------------------------- attention
// Block: 128 queries (8 warps x 16 rows) of one (b,h); 64-key tiles, online
// softmax, P as bf16 hi/lo A-frags in registers; V via ldmatrix.trans.
// 2-stage KV pipeline (correct double-barrier), 2 CTAs/SM.
#define A_Q   18432                   // 128 rows * 144B
#define A_KV  9216                    // 64 rows * 144B
#define A_ST  (4*A_KV)                // Kh, Kl, Vh, Vl = 36864
#define A_SMEM (2*A_Q + 2*A_ST)       // 110592 -> 2 CTAs/SM
#define A_TI  (NSEQ/64)               // 32 key tiles

__global__ __launch_bounds__(256, 2)
void attn()
{
    extern __shared__ char sm[];
    const uint32_t sb = s2u(sm);
    const uint32_t sQ = sb;
    const uint32_t sKV = sb + 2 * A_Q;
    const int tid = threadIdx.x, lane = tid & 31, w = tid >> 5;
    const int bh = blockIdx.y, i0 = blockIdx.x * 128;
    const size_t base = (size_t)bh * NSEQ * HS;

    // Q load (hi+lo), grouped with KV tile 0
    #pragma unroll
    for (int i = 0; i < 8; ++i) {
        int idx = tid + i * 256;
        int t = idx >> 10, r = (idx >> 3) & 127, c = idx & 7;
        const __nv_bfloat16* src = t ? g_Ql : g_Qh;
        cp16(sQ + t * A_Q + r * 144 + c * 16,
             (const char*)(src + base + (size_t)(i0 + r) * HS) + c * 16);
    }

    // KV plan
    uint32_t so[8]; const char* bp[8];
    #pragma unroll
    for (int i = 0; i < 8; ++i) {
        int idx = tid + i * 256;
        int t = idx >> 9, r = (idx >> 3) & 63, c = idx & 7;
        so[i] = t * A_KV + r * 144 + c * 16;
        const __nv_bfloat16* src = (t == 0) ? g_Kh : (t == 1) ? g_Kl
                                 : (t == 2) ? g_Vh : g_Vl;
        bp[i] = (const char*)(src + base + (size_t)r * HS) + c * 16;
    }
    #pragma unroll
    for (int i = 0; i < 8; ++i) cp16(sKV + so[i], bp[i]);   // tile 0 -> stage 0
    cp_commit();                                            // group: Q + tile0

    const int g = lane >> 3, lo8 = lane & 7;
    const uint32_t qoff = (uint32_t)(w * 16 + (g & 1) * 8 + lo8) * 144 + (g >> 1) * 16;
    const uint32_t koff = (uint32_t)((g >> 1) * 8 + lo8) * 144 + (g & 1) * 16;
    const uint32_t voff = (uint32_t)((g & 1) * 8 + lo8) * 144 + (g >> 1) * 16;

    float O[8][4];
    #pragma unroll
    for (int nf = 0; nf < 8; ++nf)
        #pragma unroll
        for (int c = 0; c < 4; ++c) O[nf][c] = 0.f;
    float m2[2] = { -1e30f, -1e30f };
    float l2[2] = { 0.f, 0.f };

    for (int jt = 0; jt < A_TI; ++jt) {
        const uint32_t st = sKV + (uint32_t)(jt & 1) * A_ST;
        // barrier 1: everyone finished reading buffer (jt+1)&1 (iter jt-1)
        __syncthreads();
        if (jt + 1 < A_TI) {
            const uint32_t nst = sKV + (uint32_t)((jt + 1) & 1) * A_ST;
            const size_t go = (size_t)(jt + 1) * (64 * HS * 2);
            #pragma unroll
            for (int i = 0; i < 8; ++i) cp16(nst + so[i], bp[i] + go);
            cp_commit();
            cp_wait<1>();          // tile jt (and Q, first iter) landed
        } else {
            cp_wait<0>();
        }
        // barrier 2: tile jt visible to all warps
        __syncthreads();

        // ---- S = Q K^T (hi/lo compensated)
        float S[8][4];
        #pragma unroll
        for (int nf = 0; nf < 8; ++nf)
            #pragma unroll
            for (int c = 0; c < 4; ++c) S[nf][c] = 0.f;

        #pragma unroll
        for (int ks = 0; ks < 4; ++ks) {
            uint32_t qh[4], ql[4];
            ldm4(qh, sQ + qoff + ks * 32);
            ldm4(ql, sQ + A_Q + qoff + ks * 32);
            #pragma unroll
            for (int n2 = 0; n2 < 4; ++n2) {
                uint32_t kh[4], kl[4];
                ldm4(kh, st + koff + n2 * 2304 + ks * 32);
                ldm4(kl, st + A_KV + koff + n2 * 2304 + ks * 32);
                #pragma unroll
                for (int e = 0; e < 2; ++e) {
                    float* cc = S[n2 * 2 + e];
                    mma16816(cc, qh, kh[e * 2], kh[e * 2 + 1]);
                    mma16816(cc, qh, kl[e * 2], kl[e * 2 + 1]);
                    mma16816(cc, ql, kh[e * 2], kh[e * 2 + 1]);
                }
            }
        }

        // ---- online softmax
        float scl[2];
        #pragma unroll
        for (int j = 0; j < 2; ++j) {
            float mx = -1e30f;
            #pragma unroll
            for (int nf = 0; nf < 8; ++nf)
                mx = fmaxf(mx, fmaxf(S[nf][j * 2], S[nf][j * 2 + 1]));
            mx = fmaxf(mx, __shfl_xor_sync(0xffffffffu, mx, 1));
            mx = fmaxf(mx, __shfl_xor_sync(0xffffffffu, mx, 2));
            const float nm = fmaxf(m2[j], mx);
            scl[j] = __expf(m2[j] - nm);
            m2[j] = nm;
            float rs = 0.f;
            #pragma unroll
            for (int nf = 0; nf < 8; ++nf) {
                float p0 = __expf(S[nf][j * 2] - nm);
                float p1 = __expf(S[nf][j * 2 + 1] - nm);
                S[nf][j * 2] = p0; S[nf][j * 2 + 1] = p1;
                rs += p0 + p1;
            }
            rs += __shfl_xor_sync(0xffffffffu, rs, 1);
            rs += __shfl_xor_sync(0xffffffffu, rs, 2);
            l2[j] = l2[j] * scl[j] + rs;
            #pragma unroll
            for (int nf = 0; nf < 8; ++nf) {
                O[nf][j * 2]     *= scl[j];
                O[nf][j * 2 + 1] *= scl[j];
            }
        }

        // ---- O += P V
        #pragma unroll
        for (int ks = 0; ks < 4; ++ks) {
            uint32_t ah[4], al[4];
            #pragma unroll
            for (int q = 0; q < 4; ++q) {
                const float* src = S[2 * ks + (q >> 1)];
                const int pr = (q & 1) * 2;
                split2(src[pr], src[pr + 1], ah[q], al[q]);
            }
            #pragma unroll
            for (int n2 = 0; n2 < 4; ++n2) {
                uint32_t vh[4], vl[4];
                ldm4t(vh, st + 2 * A_KV + voff + ks * 2304 + n2 * 32);
                ldm4t(vl, st + 3 * A_KV + voff + ks * 2304 + n2 * 32);
                #pragma unroll
                for (int e = 0; e < 2; ++e) {
                    float* oo = O[n2 * 2 + e];
                    mma16816(oo, ah, vh[e * 2], vh[e * 2 + 1]);
                    mma16816(oo, ah, vl[e * 2], vl[e * 2 + 1]);
                    mma16816(oo, al, vh[e * 2], vh[e * 2 + 1]);
                }
            }
        }
    }

    // ---- finalize
    const float inv0 = 1.f / l2[0], inv1 = 1.f / l2[1];
    const int bb = bh >> 4, hh = bh & 15;
    const int mr = i0 + w * 16 + (lane >> 2);
    const int col0 = hh * 64 + (lane & 3) * 2;
    #pragma unroll
    for (int nf = 0; nf < 8; ++nf) {
        const int col = col0 + nf * 8;
        uint32_t h, l;
        size_t d0 = (size_t)(bb * NSEQ + mr) * KDIM + col;
        split2(O[nf][0] * inv0, O[nf][1] * inv0, h, l);
        *(uint32_t*)&g_xhi[d0] = h; *(uint32_t*)&g_xlo[d0] = l;
        size_t d1 = d0 + (size_t)8 * KDIM;
        split2(O[nf][2] * inv1, O[nf][3] * inv1, h, l);
        *(uint32_t*)&g_xhi[d1] = h; *(uint32_t*)&g_xlo[d1] = l;
    }
}

// ---------------------------------------------------------------- launch
extern "C" void kernel_launch(void* const* d_in, const int* in_sizes, int n_in,
                              void* d_out, int out_size)
{
    (void)in_sizes; (void)n_in; (void)out_size;
    // metadata order: x, Wk, Wq, Wv, Wu, bu
    const float* x  = (const float*)d_in[0];
    const float* Wk = (const float*)d_in[1];
    const float* Wq = (const float*)d_in[2];
    const float* Wv = (const float*)d_in[3];
    const float* Wu = (const float*)d_in[4];
    const float* bu = (const float*)d_in[5];
    float* out = (float*)d_out;

    cudaFuncSetAttribute(hgemm, cudaFuncAttributeMaxDynamicSharedMemorySize, G_SMEM);
    cudaFuncSetAttribute(attn,  cudaFuncAttributeMaxDynamicSharedMemorySize, A_SMEM);

    const int XBLK = (MROWS * KDIM) / (4 * 256);          // 8192

    cvt_x<<<XBLK, 256>>>(x);                              // x -> hi/lo
    cvt_w<<<3 * WBLK, 256>>>(Wq, Wk, Wv);                 // packed weights
    hgemm<<<dim3(3 * KDIM / 128, MROWS / 128), 256, G_SMEM>>>(nullptr, nullptr, 0); // QKV
    cvt_w<<<WBLK, 256>>>(Wu, Wu, Wu);                     // Wu -> rows [0,1024)
    attn<<<dim3(NSEQ / 128, BSZ * NH), 256, A_SMEM>>>();  // -> g_xhi/g_xlo
    hgemm<<<dim3(KDIM / 128, MROWS / 128), 256, G_SMEM>>>(bu, out, 3);  // out
}